// round 1
// baseline (speedup 1.0000x reference)
#include <cuda_runtime.h>
#include <cuda_bf16.h>

// Shapes are fixed by the problem: x[8192,512], y[8192,512], out[8192,8192].
#define D       512
#define MAXROWS 8192
#define BM      128
#define BN      128
#define BK      16

// Scratch for row squared-norms (device globals: allocation-free).
__device__ float g_xsq[MAXROWS];
__device__ float g_ysq[MAXROWS];

// ---------------------------------------------------------------------------
// Kernel 1: row squared norms. One warp per row, float4 loads, shfl reduce.
// grid: (rows/8, 2)  block: 256 (8 warps)
// ---------------------------------------------------------------------------
__global__ void row_norms_kernel(const float* __restrict__ x,
                                 const float* __restrict__ y,
                                 int rows) {
    int warp = threadIdx.x >> 5;
    int lane = threadIdx.x & 31;
    int row  = blockIdx.x * 8 + warp;
    if (row >= rows) return;

    const float* src = (blockIdx.y == 0) ? x : y;
    const float4* p = reinterpret_cast<const float4*>(src + (size_t)row * D);

    float s = 0.f;
#pragma unroll
    for (int i = 0; i < D / 128; i++) {   // D/4 float4 per row / 32 lanes = 4
        float4 v = p[lane + 32 * i];
        s += v.x * v.x + v.y * v.y + v.z * v.z + v.w * v.w;
    }
#pragma unroll
    for (int o = 16; o > 0; o >>= 1) s += __shfl_xor_sync(0xFFFFFFFFu, s, o);

    if (lane == 0) {
        if (blockIdx.y == 0) g_xsq[row] = s;
        else                 g_ysq[row] = s;
    }
}

// ---------------------------------------------------------------------------
// Kernel 2: tiled GEMM (dot products) + fused RBF epilogue.
// Block computes a 128x128 output tile; 256 threads, each an 8x8 micro-tile.
// ---------------------------------------------------------------------------
__global__ __launch_bounds__(256)
void rbf_gemm_kernel(const float* __restrict__ X,
                     const float* __restrict__ Y,
                     float* __restrict__ O,
                     int N, int M) {
    __shared__ float As[BK][BM];
    __shared__ float Bs[BK][BN];

    const int bi = blockIdx.y * BM;  // x-row block
    const int bj = blockIdx.x * BN;  // y-row block
    const int tid = threadIdx.x;
    const int ty = tid >> 4;         // 0..15
    const int tx = tid & 15;         // 0..15

    const float* Xb = X + (size_t)bi * D;
    const float* Yb = Y + (size_t)bj * D;

    float acc[8][8];
#pragma unroll
    for (int i = 0; i < 8; i++)
#pragma unroll
        for (int j = 0; j < 8; j++) acc[i][j] = 0.f;

    for (int k0 = 0; k0 < D; k0 += BK) {
        // Load 128x16 tiles of X and Y (coalesced: 4 threads per row, 64B each)
#pragma unroll
        for (int l = 0; l < 2; l++) {
            int idx = l * 256 + tid;          // 0..511
            int row = idx >> 2;               // 0..127
            int k4  = (idx & 3) * 4;          // 0,4,8,12
            float4 a = *reinterpret_cast<const float4*>(Xb + (size_t)row * D + k0 + k4);
            As[k4 + 0][row] = a.x; As[k4 + 1][row] = a.y;
            As[k4 + 2][row] = a.z; As[k4 + 3][row] = a.w;
            float4 b = *reinterpret_cast<const float4*>(Yb + (size_t)row * D + k0 + k4);
            Bs[k4 + 0][row] = b.x; Bs[k4 + 1][row] = b.y;
            Bs[k4 + 2][row] = b.z; Bs[k4 + 3][row] = b.w;
        }
        __syncthreads();

#pragma unroll
        for (int k = 0; k < BK; k++) {
            float a[8], b[8];
            float4 a0 = *reinterpret_cast<const float4*>(&As[k][ty * 8]);
            float4 a1 = *reinterpret_cast<const float4*>(&As[k][ty * 8 + 4]);
            float4 b0 = *reinterpret_cast<const float4*>(&Bs[k][tx * 8]);
            float4 b1 = *reinterpret_cast<const float4*>(&Bs[k][tx * 8 + 4]);
            a[0]=a0.x; a[1]=a0.y; a[2]=a0.z; a[3]=a0.w;
            a[4]=a1.x; a[5]=a1.y; a[6]=a1.z; a[7]=a1.w;
            b[0]=b0.x; b[1]=b0.y; b[2]=b0.z; b[3]=b0.w;
            b[4]=b1.x; b[5]=b1.y; b[6]=b1.z; b[7]=b1.w;
#pragma unroll
            for (int i = 0; i < 8; i++)
#pragma unroll
                for (int j = 0; j < 8; j++)
                    acc[i][j] = fmaf(a[i], b[j], acc[i][j]);
        }
        __syncthreads();
    }

    // Fused RBF epilogue: out = exp(-max(||x||^2 + ||y||^2 - 2 x.y, 0))
    float nx[8], ny[8];
#pragma unroll
    for (int i = 0; i < 8; i++) nx[i] = g_xsq[bi + ty * 8 + i];
#pragma unroll
    for (int j = 0; j < 8; j++) ny[j] = g_ysq[bj + tx * 8 + j];

#pragma unroll
    for (int i = 0; i < 8; i++) {
        float4 r0, r1;
        float* r = reinterpret_cast<float*>(&r0);
#pragma unroll
        for (int j = 0; j < 8; j++) {
            float sq = nx[i] + ny[j] - 2.0f * acc[i][j];
            sq = fmaxf(sq, 0.0f);
            float e = __expf(-sq);
            if (j < 4) reinterpret_cast<float*>(&r0)[j] = e;
            else       reinterpret_cast<float*>(&r1)[j - 4] = e;
        }
        (void)r;
        size_t orow = (size_t)(bi + ty * 8 + i) * M + bj + tx * 8;
        *reinterpret_cast<float4*>(O + orow)     = r0;
        *reinterpret_cast<float4*>(O + orow + 4) = r1;
    }
}

// ---------------------------------------------------------------------------
extern "C" void kernel_launch(void* const* d_in, const int* in_sizes, int n_in,
                              void* d_out, int out_size) {
    const float* x = (const float*)d_in[0];
    const float* y = (const float*)d_in[1];
    float* out = (float*)d_out;

    int N = in_sizes[0] / D;   // 8192
    int M = in_sizes[1] / D;   // 8192

    {
        dim3 grid((N + 7) / 8, 2);
        row_norms_kernel<<<grid, 256>>>(x, y, N);
    }
    {
        dim3 grid(M / BN, N / BM);
        rbf_gemm_kernel<<<grid, 256>>>(x, y, out, N, M);
    }
}

// round 4
// speedup vs baseline: 5.8726x; 5.8726x over previous
#include <cuda_runtime.h>
#include <cuda_bf16.h>
#include <cstdint>

// x[8192,512] fp32, y[8192,512] fp32, out[8192,8192] fp32 (row-major).
#define DDIM   512
#define NROWS  8192
#define BM     128
#define BN     128
#define BK     32
#define NK     (DDIM / BK)          // 16 k-iterations
#define STAGES 4

#define ROWB   80                   // padded row stride in bytes (32 bf16 = 64B + 16B pad)
#define ABYTES (BM * ROWB)          // 10240
#define BBYTES (BN * ROWB)          // 10240
#define STAGE_BYTES (ABYTES + BBYTES)          // 20480
#define SMEM_DYN (STAGES * STAGE_BYTES)        // 81920

__device__ __align__(16) __nv_bfloat16 g_xb[NROWS * DDIM];
__device__ __align__(16) __nv_bfloat16 g_yb[NROWS * DDIM];
__device__ float g_xsq[NROWS];
__device__ float g_ysq[NROWS];

static __device__ __forceinline__ uint32_t s2u(const void* p) {
    uint32_t a;
    asm("{ .reg .u64 t; cvta.to.shared.u64 t, %1; cvt.u32.u64 %0, t; }"
        : "=r"(a) : "l"(p));
    return a;
}

static __device__ __forceinline__ void cpa16(uint32_t s, const void* g) {
    asm volatile("cp.async.cg.shared.global [%0], [%1], 16;"
                 :: "r"(s), "l"(g) : "memory");
}

#define LDSM_X4(r0, r1, r2, r3, addr) \
    asm volatile("ldmatrix.sync.aligned.m8n8.x4.shared.b16 {%0,%1,%2,%3}, [%4];" \
                 : "=r"(r0), "=r"(r1), "=r"(r2), "=r"(r3) : "r"(addr))

#define MMA16816(d, a0, a1, a2, a3, b0, b1) \
    asm volatile("mma.sync.aligned.m16n8k16.row.col.f32.bf16.bf16.f32 " \
                 "{%0,%1,%2,%3}, {%4,%5,%6,%7}, {%8,%9}, {%0,%1,%2,%3};" \
                 : "+f"((d)[0]), "+f"((d)[1]), "+f"((d)[2]), "+f"((d)[3]) \
                 : "r"(a0), "r"(a1), "r"(a2), "r"(a3), "r"(b0), "r"(b1))

// ---------------------------------------------------------------------------
// Kernel 1: fp32 -> bf16 + row squared norms. One warp per row.
// ---------------------------------------------------------------------------
__global__ __launch_bounds__(256)
void prep_kernel(const float* __restrict__ x, const float* __restrict__ y) {
    int warp = threadIdx.x >> 5;
    int lane = threadIdx.x & 31;
    int gr   = blockIdx.x * 8 + warp;       // 0..16383
    int row  = gr & (NROWS - 1);
    bool isy = gr >= NROWS;

    const float* src = isy ? y : x;
    __nv_bfloat16* dst = isy ? g_yb : g_xb;
    const float4* p = reinterpret_cast<const float4*>(src + (size_t)row * DDIM);

    float s = 0.f;
#pragma unroll
    for (int i = 0; i < 4; i++) {
        float4 v = p[lane + 32 * i];
        s += v.x * v.x + v.y * v.y + v.z * v.z + v.w * v.w;
        __nv_bfloat162 lo = __floats2bfloat162_rn(v.x, v.y);
        __nv_bfloat162 hi = __floats2bfloat162_rn(v.z, v.w);
        uint2 u;
        u.x = *reinterpret_cast<uint32_t*>(&lo);
        u.y = *reinterpret_cast<uint32_t*>(&hi);
        *reinterpret_cast<uint2*>(dst + (size_t)row * DDIM + 4 * (lane + 32 * i)) = u;
    }
#pragma unroll
    for (int o = 16; o > 0; o >>= 1) s += __shfl_xor_sync(0xFFFFFFFFu, s, o);
    if (lane == 0) (isy ? g_ysq : g_xsq)[row] = s;
}

// ---------------------------------------------------------------------------
// Kernel 2: bf16 HMMA GEMM (128x128 tile) + fused RBF epilogue.
// 8 warps: wm = wid>>1 (4 in M, 32 rows each), wn = wid&1 (2 in N, 64 cols).
// Warp tile 32x64 = 2 m-tiles x 8 n-tiles of m16n8k16.
// ---------------------------------------------------------------------------
__global__ __launch_bounds__(256, 2)
void rbf_mma_kernel(float* __restrict__ O) {
    extern __shared__ char smem[];
    __shared__ float snx[BM];
    __shared__ float sny[BN];

    const uint32_t sd = s2u(smem);
    const int tid  = threadIdx.x;
    const int lane = tid & 31;
    const int wid  = tid >> 5;
    const int wm   = wid >> 1;        // 0..3
    const int wn   = wid & 1;         // 0..1
    const int bi   = blockIdx.y * BM;
    const int bj   = blockIdx.x * BN;

    // per-thread cp.async indices: i = tid + t*256; r = i>>2; c = i&3
    const int r0 = tid >> 2, c0 = tid & 3;

    // ldmatrix per-thread byte offsets (within a stage)
    // A: row = wm*32 + mt*16 + (lane&15), chunk = lane>>4
    const uint32_t a_off = (uint32_t)((wm * 32 + (lane & 15)) * ROWB + (lane >> 4) * 16);
    // B: row = wn*64 + ntp*16 + ((lane>>4)<<3) + (lane&7), chunk = (lane>>3)&1
    const uint32_t b_off = (uint32_t)((wn * 64 + ((lane >> 4) << 3) + (lane & 7)) * ROWB
                                      + ((lane >> 3) & 1) * 16);

    auto load_stage = [&](int slot, int k0) {
        uint32_t sa = sd + slot * STAGE_BYTES;
        const __nv_bfloat16* gx = g_xb + (size_t)bi * DDIM + k0;
        const __nv_bfloat16* gy = g_yb + (size_t)bj * DDIM + k0;
#pragma unroll
        for (int t = 0; t < 2; t++) {
            int r = r0 + t * 64;
            cpa16(sa + r * ROWB + c0 * 16,          gx + (size_t)r * DDIM + c0 * 8);
            cpa16(sa + ABYTES + r * ROWB + c0 * 16, gy + (size_t)r * DDIM + c0 * 8);
        }
        asm volatile("cp.async.commit_group;" ::: "memory");
    };

    float d[64];
#pragma unroll
    for (int i = 0; i < 64; i++) d[i] = 0.f;

    // prologue: fill stages 0..2
    load_stage(0, 0);
    load_stage(1, BK);
    load_stage(2, 2 * BK);

    // norms staging (independent of the pipeline)
    if (tid < BM) snx[tid] = g_xsq[bi + tid];
    else if (tid < BM + BN) sny[tid - BM] = g_ysq[bj + (tid - BM)];

#pragma unroll 1
    for (int it = 0; it < NK; ++it) {
        if (it < NK - 2) asm volatile("cp.async.wait_group 2;" ::: "memory");
        else if (it == NK - 2) asm volatile("cp.async.wait_group 1;" ::: "memory");
        else asm volatile("cp.async.wait_group 0;" ::: "memory");
        __syncthreads();

        if (it + 3 < NK) load_stage((it + 3) & (STAGES - 1), (it + 3) * BK);

        const uint32_t sa = sd + (it & (STAGES - 1)) * STAGE_BYTES;
        const uint32_t sbB = sa + ABYTES;

#pragma unroll
        for (int ks = 0; ks < 2; ks++) {
            uint32_t a[2][4];
#pragma unroll
            for (int mt = 0; mt < 2; mt++)
                LDSM_X4(a[mt][0], a[mt][1], a[mt][2], a[mt][3],
                        sa + a_off + mt * 16 * ROWB + ks * 32);
            uint32_t b[4][4];
#pragma unroll
            for (int ntp = 0; ntp < 4; ntp++)
                LDSM_X4(b[ntp][0], b[ntp][1], b[ntp][2], b[ntp][3],
                        sbB + b_off + ntp * 16 * ROWB + ks * 32);
#pragma unroll
            for (int mt = 0; mt < 2; mt++)
#pragma unroll
                for (int ntp = 0; ntp < 4; ntp++) {
                    MMA16816(&d[mt * 32 + (2 * ntp) * 4],
                             a[mt][0], a[mt][1], a[mt][2], a[mt][3],
                             b[ntp][0], b[ntp][1]);
                    MMA16816(&d[mt * 32 + (2 * ntp + 1) * 4],
                             a[mt][0], a[mt][1], a[mt][2], a[mt][3],
                             b[ntp][2], b[ntp][3]);
                }
        }
    }

    __syncthreads();  // snx/sny visible (and pipeline fully drained)

    // ---- fused epilogue: exp(-max(nx + ny - 2*dot, 0)), float2 stores ----
    const int rbase = wm * 32 + (lane >> 2);
    const int cbase = wn * 64 + (lane & 3) * 2;
#pragma unroll
    for (int mt = 0; mt < 2; mt++) {
#pragma unroll
        for (int half = 0; half < 2; half++) {
            const int row = rbase + mt * 16 + half * 8;
            const float nx = snx[row];
            float* orow = O + (size_t)(bi + row) * 8192 + bj;
#pragma unroll
            for (int nt = 0; nt < 8; nt++) {
                const int col = cbase + nt * 8;
                float d0 = d[mt * 32 + nt * 4 + half * 2 + 0];
                float d1 = d[mt * 32 + nt * 4 + half * 2 + 1];
                float s0 = fmaxf(fmaf(-2.f, d0, nx + sny[col]),     0.f);
                float s1 = fmaxf(fmaf(-2.f, d1, nx + sny[col + 1]), 0.f);
                float2 e = make_float2(__expf(-s0), __expf(-s1));
                *reinterpret_cast<float2*>(orow + col) = e;
            }
        }
    }
}

// ---------------------------------------------------------------------------
extern "C" void kernel_launch(void* const* d_in, const int* in_sizes, int n_in,
                              void* d_out, int out_size) {
    const float* x = (const float*)d_in[0];
    const float* y = (const float*)d_in[1];
    float* out = (float*)d_out;

    cudaFuncSetAttribute(rbf_mma_kernel,
                         cudaFuncAttributeMaxDynamicSharedMemorySize, SMEM_DYN);

    prep_kernel<<<NROWS * 2 / 8, 256>>>(x, y);
    rbf_mma_kernel<<<dim3(8192 / BN, 8192 / BM), 256, SMEM_DYN>>>(out);
}

// round 6
// speedup vs baseline: 6.5730x; 1.1193x over previous
#include <cuda_runtime.h>
#include <cuda_bf16.h>
#include <cstdint>

// x[8192,512] fp32, y[8192,512] fp32, out[8192,8192] fp32 (row-major).
#define DDIM   512
#define NROWS  8192
#define BM     128
#define BN     128
#define BK     32
#define NK     (DDIM / BK)          // 16 k-iterations
#define STAGES 4

#define ROWB   80                   // padded row stride (32 bf16 = 64B + 16B pad)
#define ABYTES (BM * ROWB)          // 10240
#define STAGE_BYTES (2 * ABYTES)    // 20480
#define SMEM_DYN (STAGES * STAGE_BYTES)  // 81920

__device__ __align__(16) __nv_bfloat16 g_xb[NROWS * DDIM];
__device__ __align__(16) __nv_bfloat16 g_yb[NROWS * DDIM];
__device__ float g_xsq[NROWS];
__device__ float g_ysq[NROWS];

static __device__ __forceinline__ uint32_t s2u(const void* p) {
    uint32_t a;
    asm("{ .reg .u64 t; cvta.to.shared.u64 t, %1; cvt.u32.u64 %0, t; }"
        : "=r"(a) : "l"(p));
    return a;
}

static __device__ __forceinline__ void cpa16(uint32_t s, const void* g) {
    asm volatile("cp.async.cg.shared.global [%0], [%1], 16;"
                 :: "r"(s), "l"(g) : "memory");
}

#define LDSM_X4(r0, r1, r2, r3, addr) \
    asm volatile("ldmatrix.sync.aligned.m8n8.x4.shared.b16 {%0,%1,%2,%3}, [%4];" \
                 : "=r"(r0), "=r"(r1), "=r"(r2), "=r"(r3) : "r"(addr))

#define MMA16816(d, a0, a1, a2, a3, b0, b1) \
    asm volatile("mma.sync.aligned.m16n8k16.row.col.f32.bf16.bf16.f32 " \
                 "{%0,%1,%2,%3}, {%4,%5,%6,%7}, {%8,%9}, {%0,%1,%2,%3};" \
                 : "+f"((d)[0]), "+f"((d)[1]), "+f"((d)[2]), "+f"((d)[3]) \
                 : "r"(a0), "r"(a1), "r"(a2), "r"(a3), "r"(b0), "r"(b1))

// ---------------------------------------------------------------------------
// Kernel 1: fp32 -> bf16 + row squared norms. One warp per row.
// ---------------------------------------------------------------------------
__global__ __launch_bounds__(256)
void prep_kernel(const float* __restrict__ x, const float* __restrict__ y) {
    int warp = threadIdx.x >> 5;
    int lane = threadIdx.x & 31;
    int gr   = blockIdx.x * 8 + warp;       // 0..16383
    int row  = gr & (NROWS - 1);
    bool isy = gr >= NROWS;

    const float* src = isy ? y : x;
    __nv_bfloat16* dst = isy ? g_yb : g_xb;
    const float4* p = reinterpret_cast<const float4*>(src + (size_t)row * DDIM);

    float s = 0.f;
#pragma unroll
    for (int i = 0; i < 4; i++) {
        float4 v = p[lane + 32 * i];
        s += v.x * v.x + v.y * v.y + v.z * v.z + v.w * v.w;
        __nv_bfloat162 lo = __floats2bfloat162_rn(v.x, v.y);
        __nv_bfloat162 hi = __floats2bfloat162_rn(v.z, v.w);
        uint2 u;
        u.x = *reinterpret_cast<uint32_t*>(&lo);
        u.y = *reinterpret_cast<uint32_t*>(&hi);
        *reinterpret_cast<uint2*>(dst + (size_t)row * DDIM + 4 * (lane + 32 * i)) = u;
    }
#pragma unroll
    for (int o = 16; o > 0; o >>= 1) s += __shfl_xor_sync(0xFFFFFFFFu, s, o);
    if (lane == 0) (isy ? g_ysq : g_xsq)[row] = s;
}

// ---------------------------------------------------------------------------
// Kernel 2: bf16 HMMA GEMM (128x128 CTA tile, 64x64 warp tile) + RBF epilogue.
// 4 warps: wm = wid>>1 (2 in M), wn = wid&1 (2 in N).
// Warp tile 64x64 = 4 m-tiles x 8 n-tiles of m16n8k16 = 32 MMAs per k-slice.
// ---------------------------------------------------------------------------
__global__ __launch_bounds__(128, 2)
void rbf_mma_kernel(float* __restrict__ O) {
    extern __shared__ char smem[];
    __shared__ float snx[BM];
    __shared__ float sny[BN];

    const uint32_t sd = s2u(smem);
    const int tid  = threadIdx.x;
    const int lane = tid & 31;
    const int wid  = tid >> 5;       // 0..3
    const int wm   = wid >> 1;       // 0..1
    const int wn   = wid & 1;        // 0..1
    const int bi   = blockIdx.y * BM;
    const int bj   = blockIdx.x * BN;

    // cp.async indices: r0 = tid>>2 (0..31), c0 = tid&3
    const int r0 = tid >> 2, c0 = tid & 3;

    // ldmatrix byte offsets within a stage
    // A: row = wm*64 + mt*16 + (lane&15), 16B chunk = lane>>4
    const uint32_t a_off = (uint32_t)((wm * 64 + (lane & 15)) * ROWB + (lane >> 4) * 16);
    // B: row = wn*64 + ntp*16 + ((lane>>4)<<3) + (lane&7), chunk = (lane>>3)&1
    const uint32_t b_off = (uint32_t)((wn * 64 + ((lane >> 4) << 3) + (lane & 7)) * ROWB
                                      + ((lane >> 3) & 1) * 16);

    auto load_stage = [&](int slot, int k0) {
        uint32_t sa = sd + slot * STAGE_BYTES;
        const __nv_bfloat16* gx = g_xb + (size_t)bi * DDIM + k0;
        const __nv_bfloat16* gy = g_yb + (size_t)bj * DDIM + k0;
#pragma unroll
        for (int t = 0; t < 4; t++) {
            int r = r0 + t * 32;
            cpa16(sa + r * ROWB + c0 * 16,          gx + (size_t)r * DDIM + c0 * 8);
            cpa16(sa + ABYTES + r * ROWB + c0 * 16, gy + (size_t)r * DDIM + c0 * 8);
        }
        asm volatile("cp.async.commit_group;" ::: "memory");
    };

    float d[128];
#pragma unroll
    for (int i = 0; i < 128; i++) d[i] = 0.f;

    // prologue: fill stages 0..2
    load_stage(0, 0);
    load_stage(1, BK);
    load_stage(2, 2 * BK);

    // norms staging (128 threads, 128 entries each)
    snx[tid] = g_xsq[bi + tid];
    sny[tid] = g_ysq[bj + tid];

#pragma unroll 1
    for (int it = 0; it < NK; ++it) {
        if (it < NK - 2) asm volatile("cp.async.wait_group 2;" ::: "memory");
        else if (it == NK - 2) asm volatile("cp.async.wait_group 1;" ::: "memory");
        else asm volatile("cp.async.wait_group 0;" ::: "memory");
        __syncthreads();

        if (it + 3 < NK) load_stage((it + 3) & (STAGES - 1), (it + 3) * BK);

        const uint32_t sa  = sd + (it & (STAGES - 1)) * STAGE_BYTES;
        const uint32_t sbB = sa + ABYTES;

#pragma unroll
        for (int ks = 0; ks < 2; ks++) {
            uint32_t a[4][4];
#pragma unroll
            for (int mt = 0; mt < 4; mt++)
                LDSM_X4(a[mt][0], a[mt][1], a[mt][2], a[mt][3],
                        sa + a_off + mt * 16 * ROWB + ks * 32);
            uint32_t b[4][4];
#pragma unroll
            for (int ntp = 0; ntp < 4; ntp++)
                LDSM_X4(b[ntp][0], b[ntp][1], b[ntp][2], b[ntp][3],
                        sbB + b_off + ntp * 16 * ROWB + ks * 32);
#pragma unroll
            for (int mt = 0; mt < 4; mt++)
#pragma unroll
                for (int ntp = 0; ntp < 4; ntp++) {
                    MMA16816(&d[(mt * 8 + 2 * ntp) * 4],
                             a[mt][0], a[mt][1], a[mt][2], a[mt][3],
                             b[ntp][0], b[ntp][1]);
                    MMA16816(&d[(mt * 8 + 2 * ntp + 1) * 4],
                             a[mt][0], a[mt][1], a[mt][2], a[mt][3],
                             b[ntp][2], b[ntp][3]);
                }
        }
    }

    __syncthreads();  // pipeline drained; snx/sny visible

    // ---- fused epilogue: exp(-max(nx + ny - 2*dot, 0)), float2 stores ----
    const int rq = lane >> 2;
    const int cq = (lane & 3) * 2;
#pragma unroll
    for (int mt = 0; mt < 4; mt++) {
#pragma unroll
        for (int half = 0; half < 2; half++) {
            const int row = wm * 64 + mt * 16 + half * 8 + rq;
            const float nx = snx[row];
            float* orow = O + (size_t)(bi + row) * 8192 + bj;
#pragma unroll
            for (int n8 = 0; n8 < 8; n8++) {
                const int col = wn * 64 + n8 * 8 + cq;
                float d0 = d[(mt * 8 + n8) * 4 + half * 2 + 0];
                float d1 = d[(mt * 8 + n8) * 4 + half * 2 + 1];
                float s0 = fmaxf(fmaf(-2.f, d0, nx + sny[col]),     0.f);
                float s1 = fmaxf(fmaf(-2.f, d1, nx + sny[col + 1]), 0.f);
                float2 e = make_float2(__expf(-s0), __expf(-s1));
                *reinterpret_cast<float2*>(orow + col) = e;
            }
        }
    }
}

// ---------------------------------------------------------------------------
extern "C" void kernel_launch(void* const* d_in, const int* in_sizes, int n_in,
                              void* d_out, int out_size) {
    const float* x = (const float*)d_in[0];
    const float* y = (const float*)d_in[1];
    float* out = (float*)d_out;

    cudaFuncSetAttribute(rbf_mma_kernel,
                         cudaFuncAttributeMaxDynamicSharedMemorySize, SMEM_DYN);

    prep_kernel<<<NROWS * 2 / 8, 256>>>(x, y);
    rbf_mma_kernel<<<dim3(8192 / BN, 8192 / BM), 128, SMEM_DYN>>>(out);
}

// round 9
// speedup vs baseline: 6.6233x; 1.0077x over previous
#include <cuda_runtime.h>
#include <cuda_bf16.h>
#include <cstdint>

// x[8192,512] fp32, y[8192,512] fp32, out[8192,8192] fp32 (row-major).
#define DDIM   512
#define NROWS  8192
#define BM     128
#define BN     128
#define BK     32
#define NK     (DDIM / BK)          // 16 k-iterations
#define STAGES 4

#define ROWB   80                   // padded row stride (32 bf16 = 64B + 16B pad)
#define ABYTES (BM * ROWB)          // 10240
#define STAGE_BYTES (2 * ABYTES)    // 20480
#define SMEM_DYN (STAGES * STAGE_BYTES)  // 81920

__device__ __align__(16) __nv_bfloat16 g_xb[NROWS * DDIM];
__device__ __align__(16) __nv_bfloat16 g_yb[NROWS * DDIM];
__device__ float g_xsq[NROWS];
__device__ float g_ysq[NROWS];

static __device__ __forceinline__ uint32_t s2u(const void* p) {
    uint32_t a;
    asm("{ .reg .u64 t; cvta.to.shared.u64 t, %1; cvt.u32.u64 %0, t; }"
        : "=r"(a) : "l"(p));
    return a;
}

static __device__ __forceinline__ void cpa16(uint32_t s, const void* g) {
    asm volatile("cp.async.cg.shared.global [%0], [%1], 16;"
                 :: "r"(s), "l"(g) : "memory");
}

#define LDSM_X4(r0, r1, r2, r3, addr) \
    asm volatile("ldmatrix.sync.aligned.m8n8.x4.shared.b16 {%0,%1,%2,%3}, [%4];" \
                 : "=r"(r0), "=r"(r1), "=r"(r2), "=r"(r3) : "r"(addr))

#define MMA16816(d, a0, a1, a2, a3, b0, b1) \
    asm volatile("mma.sync.aligned.m16n8k16.row.col.f32.bf16.bf16.f32 " \
                 "{%0,%1,%2,%3}, {%4,%5,%6,%7}, {%8,%9}, {%0,%1,%2,%3};" \
                 : "+f"((d)[0]), "+f"((d)[1]), "+f"((d)[2]), "+f"((d)[3]) \
                 : "r"(a0), "r"(a1), "r"(a2), "r"(a3), "r"(b0), "r"(b1))

// ---------------------------------------------------------------------------
// Kernel 1: fp32 -> bf16 + row squared norms. One warp per row.
// ---------------------------------------------------------------------------
__global__ __launch_bounds__(256)
void prep_kernel(const float* __restrict__ x, const float* __restrict__ y) {
    int warp = threadIdx.x >> 5;
    int lane = threadIdx.x & 31;
    int gr   = blockIdx.x * 8 + warp;       // 0..16383
    int row  = gr & (NROWS - 1);
    bool isy = gr >= NROWS;

    const float* src = isy ? y : x;
    __nv_bfloat16* dst = isy ? g_yb : g_xb;
    const float4* p = reinterpret_cast<const float4*>(src + (size_t)row * DDIM);

    float s = 0.f;
#pragma unroll
    for (int i = 0; i < 4; i++) {
        float4 v = p[lane + 32 * i];
        s += v.x * v.x + v.y * v.y + v.z * v.z + v.w * v.w;
        __nv_bfloat162 lo = __floats2bfloat162_rn(v.x, v.y);
        __nv_bfloat162 hi = __floats2bfloat162_rn(v.z, v.w);
        uint2 u;
        u.x = *reinterpret_cast<uint32_t*>(&lo);
        u.y = *reinterpret_cast<uint32_t*>(&hi);
        *reinterpret_cast<uint2*>(dst + (size_t)row * DDIM + 4 * (lane + 32 * i)) = u;
    }
#pragma unroll
    for (int o = 16; o > 0; o >>= 1) s += __shfl_xor_sync(0xFFFFFFFFu, s, o);
    if (lane == 0) (isy ? g_ysq : g_xsq)[row] = s;
}

// ---------------------------------------------------------------------------
// Kernel 2: bf16 HMMA GEMM (128x128 CTA tile, 64x64 warp tile) + RBF epilogue.
// 4 warps: wm = wid>>1 (2 in M), wn = wid&1 (2 in N).
// Per k-iteration: issue ALL 16 LDSM (both k-slices, double-buffered frags),
// then 2 x 32 MMAs. Slice-1 LDSM latency hides under slice-0 MMA burst.
// ---------------------------------------------------------------------------
__global__ __launch_bounds__(128, 2)
void rbf_mma_kernel(float* __restrict__ O) {
    extern __shared__ char smem[];
    __shared__ float snx[BM];
    __shared__ float sny[BN];

    const uint32_t sd = s2u(smem);
    const int tid  = threadIdx.x;
    const int lane = tid & 31;
    const int wid  = tid >> 5;       // 0..3
    const int wm   = wid >> 1;       // 0..1
    const int wn   = wid & 1;        // 0..1
    const int bi   = blockIdx.y * BM;
    const int bj   = blockIdx.x * BN;

    const int r0 = tid >> 2, c0 = tid & 3;

    // ldmatrix byte offsets within a stage
    const uint32_t a_off = (uint32_t)((wm * 64 + (lane & 15)) * ROWB + (lane >> 4) * 16);
    const uint32_t b_off = (uint32_t)((wn * 64 + ((lane >> 4) << 3) + (lane & 7)) * ROWB
                                      + ((lane >> 3) & 1) * 16);

    auto load_stage = [&](int slot, int k0) {
        uint32_t sa = sd + slot * STAGE_BYTES;
        const __nv_bfloat16* gx = g_xb + (size_t)bi * DDIM + k0;
        const __nv_bfloat16* gy = g_yb + (size_t)bj * DDIM + k0;
#pragma unroll
        for (int t = 0; t < 4; t++) {
            int r = r0 + t * 32;
            cpa16(sa + r * ROWB + c0 * 16,          gx + (size_t)r * DDIM + c0 * 8);
            cpa16(sa + ABYTES + r * ROWB + c0 * 16, gy + (size_t)r * DDIM + c0 * 8);
        }
        asm volatile("cp.async.commit_group;" ::: "memory");
    };

    float d[128];
#pragma unroll
    for (int i = 0; i < 128; i++) d[i] = 0.f;

    // prologue: fill stages 0..2
    load_stage(0, 0);
    load_stage(1, BK);
    load_stage(2, 2 * BK);

    // norms staging
    snx[tid] = g_xsq[bi + tid];
    sny[tid] = g_ysq[bj + tid];

    uint32_t Af[2][4][4], Bf[2][4][4];

#pragma unroll 1
    for (int it = 0; it < NK; ++it) {
        if (it < NK - 2) asm volatile("cp.async.wait_group 2;" ::: "memory");
        else if (it == NK - 2) asm volatile("cp.async.wait_group 1;" ::: "memory");
        else asm volatile("cp.async.wait_group 0;" ::: "memory");
        __syncthreads();

        if (it + 3 < NK) load_stage((it + 3) & (STAGES - 1), (it + 3) * BK);

        const uint32_t sa  = sd + (it & (STAGES - 1)) * STAGE_BYTES;
        const uint32_t sbB = sa + ABYTES;

        // Issue ALL fragment loads for both k-slices up front.
#pragma unroll
        for (int ks = 0; ks < 2; ks++) {
#pragma unroll
            for (int mt = 0; mt < 4; mt++)
                LDSM_X4(Af[ks][mt][0], Af[ks][mt][1], Af[ks][mt][2], Af[ks][mt][3],
                        sa + a_off + mt * 16 * ROWB + ks * 32);
#pragma unroll
            for (int ntp = 0; ntp < 4; ntp++)
                LDSM_X4(Bf[ks][ntp][0], Bf[ks][ntp][1], Bf[ks][ntp][2], Bf[ks][ntp][3],
                        sbB + b_off + ntp * 16 * ROWB + ks * 32);
        }

#pragma unroll
        for (int ks = 0; ks < 2; ks++)
#pragma unroll
            for (int mt = 0; mt < 4; mt++)
#pragma unroll
                for (int ntp = 0; ntp < 4; ntp++) {
                    MMA16816(&d[(mt * 8 + 2 * ntp) * 4],
                             Af[ks][mt][0], Af[ks][mt][1], Af[ks][mt][2], Af[ks][mt][3],
                             Bf[ks][ntp][0], Bf[ks][ntp][1]);
                    MMA16816(&d[(mt * 8 + 2 * ntp + 1) * 4],
                             Af[ks][mt][0], Af[ks][mt][1], Af[ks][mt][2], Af[ks][mt][3],
                             Bf[ks][ntp][2], Bf[ks][ntp][3]);
                }
    }

    __syncthreads();  // pipeline drained; snx/sny visible

    // ---- fused epilogue: exp(-max(nx + ny - 2*dot, 0)), float2 stores ----
    const int rq = lane >> 2;
    const int cq = (lane & 3) * 2;
#pragma unroll
    for (int mt = 0; mt < 4; mt++) {
#pragma unroll
        for (int half = 0; half < 2; half++) {
            const int row = wm * 64 + mt * 16 + half * 8 + rq;
            const float nx = snx[row];
            float* orow = O + (size_t)(bi + row) * 8192 + bj;
#pragma unroll
            for (int n8 = 0; n8 < 8; n8++) {
                const int col = wn * 64 + n8 * 8 + cq;
                float d0 = d[(mt * 8 + n8) * 4 + half * 2 + 0];
                float d1 = d[(mt * 8 + n8) * 4 + half * 2 + 1];
                float s0 = fmaxf(fmaf(-2.f, d0, nx + sny[col]),     0.f);
                float s1 = fmaxf(fmaf(-2.f, d1, nx + sny[col + 1]), 0.f);
                float2 e = make_float2(__expf(-s0), __expf(-s1));
                *reinterpret_cast<float2*>(orow + col) = e;
            }
        }
    }
}

// ---------------------------------------------------------------------------
extern "C" void kernel_launch(void* const* d_in, const int* in_sizes, int n_in,
                              void* d_out, int out_size) {
    const float* x = (const float*)d_in[0];
    const float* y = (const float*)d_in[1];
    float* out = (float*)d_out;

    cudaFuncSetAttribute(rbf_mma_kernel,
                         cudaFuncAttributeMaxDynamicSharedMemorySize, SMEM_DYN);

    prep_kernel<<<NROWS * 2 / 8, 256>>>(x, y);
    rbf_mma_kernel<<<dim3(8192 / BN, 8192 / BM), 128, SMEM_DYN>>>(out);
}

// round 10
// speedup vs baseline: 6.7819x; 1.0239x over previous
#include <cuda_runtime.h>
#include <cuda_bf16.h>
#include <cstdint>

// x[8192,512] fp32, y[8192,512] fp32, out[8192,8192] fp32 (row-major).
#define DDIM   512
#define NROWS  8192
#define BM     128
#define BN     128
#define BK     64                   // 64 e4m3 elements (= 64 bytes) per k-iter
#define NK     (DDIM / BK)          // 8 k-iterations
#define STAGES 4

#define ROWB   80                   // padded row stride (64B data + 16B pad)
#define ABYTES (BM * ROWB)          // 10240
#define STAGE_BYTES (2 * ABYTES)    // 20480
#define SMEM_DYN (STAGES * STAGE_BYTES)  // 81920

__device__ __align__(16) uint8_t g_x8[NROWS * DDIM];
__device__ __align__(16) uint8_t g_y8[NROWS * DDIM];
__device__ float g_xsq[NROWS];
__device__ float g_ysq[NROWS];

static __device__ __forceinline__ uint32_t s2u(const void* p) {
    uint32_t a;
    asm("{ .reg .u64 t; cvta.to.shared.u64 t, %1; cvt.u32.u64 %0, t; }"
        : "=r"(a) : "l"(p));
    return a;
}

static __device__ __forceinline__ void cpa16(uint32_t s, const void* g) {
    asm volatile("cp.async.cg.shared.global [%0], [%1], 16;"
                 :: "r"(s), "l"(g) : "memory");
}

// pack 4 fp32 -> 4 e4m3 bytes (b0..b3 = v.x..v.w)
static __device__ __forceinline__ uint32_t f4_to_e4m3x4(float4 v) {
    uint16_t lo, hi;
    asm("cvt.rn.satfinite.e4m3x2.f32 %0, %1, %2;" : "=h"(lo) : "f"(v.y), "f"(v.x));
    asm("cvt.rn.satfinite.e4m3x2.f32 %0, %1, %2;" : "=h"(hi) : "f"(v.w), "f"(v.z));
    return ((uint32_t)hi << 16) | lo;
}

#define LDSM_X4(r0, r1, r2, r3, addr) \
    asm volatile("ldmatrix.sync.aligned.m8n8.x4.shared.b16 {%0,%1,%2,%3}, [%4];" \
                 : "=r"(r0), "=r"(r1), "=r"(r2), "=r"(r3) : "r"(addr))

// fp8 MMA: m16n8k32, e4m3 x e4m3 -> f32
#define MMA16832(d, a0, a1, a2, a3, b0, b1) \
    asm volatile("mma.sync.aligned.m16n8k32.row.col.f32.e4m3.e4m3.f32 " \
                 "{%0,%1,%2,%3}, {%4,%5,%6,%7}, {%8,%9}, {%0,%1,%2,%3};" \
                 : "+f"((d)[0]), "+f"((d)[1]), "+f"((d)[2]), "+f"((d)[3]) \
                 : "r"(a0), "r"(a1), "r"(a2), "r"(a3), "r"(b0), "r"(b1))

// ---------------------------------------------------------------------------
// Kernel 1: fp32 -> e4m3 + row squared norms (fp32). One warp per row.
// ---------------------------------------------------------------------------
__global__ __launch_bounds__(256)
void prep_kernel(const float* __restrict__ x, const float* __restrict__ y) {
    int warp = threadIdx.x >> 5;
    int lane = threadIdx.x & 31;
    int gr   = blockIdx.x * 8 + warp;       // 0..16383
    int row  = gr & (NROWS - 1);
    bool isy = gr >= NROWS;

    const float* src = isy ? y : x;
    uint8_t* dst = isy ? g_y8 : g_x8;
    const float4* p = reinterpret_cast<const float4*>(src + (size_t)row * DDIM);

    float s = 0.f;
#pragma unroll
    for (int i = 0; i < 4; i++) {
        float4 v = p[lane + 32 * i];
        s += v.x * v.x + v.y * v.y + v.z * v.z + v.w * v.w;
        uint32_t packed = f4_to_e4m3x4(v);
        *reinterpret_cast<uint32_t*>(dst + (size_t)row * DDIM + 4 * (lane + 32 * i)) = packed;
    }
#pragma unroll
    for (int o = 16; o > 0; o >>= 1) s += __shfl_xor_sync(0xFFFFFFFFu, s, o);
    if (lane == 0) (isy ? g_ysq : g_xsq)[row] = s;
}

// ---------------------------------------------------------------------------
// Kernel 2: e4m3 HMMA GEMM (128x128 CTA tile, 64x64 warp tile) + RBF epilogue.
// 4 warps: wm = wid>>1 (2 in M), wn = wid&1 (2 in N).
// Per k-iteration (64 K-elements): 16 LDSM + 2 slices x 32 MMAs (m16n8k32).
// ---------------------------------------------------------------------------
__global__ __launch_bounds__(128, 2)
void rbf_mma_kernel(float* __restrict__ O) {
    extern __shared__ char smem[];
    __shared__ float snx[BM];
    __shared__ float sny[BN];

    const uint32_t sd = s2u(smem);
    const int tid  = threadIdx.x;
    const int lane = tid & 31;
    const int wid  = tid >> 5;       // 0..3
    const int wm   = wid >> 1;       // 0..1
    const int wn   = wid & 1;        // 0..1
    const int bi   = blockIdx.y * BM;
    const int bj   = blockIdx.x * BN;

    const int r0 = tid >> 2, c0 = tid & 3;

    // ldmatrix byte offsets within a stage (identical geometry to bf16 version)
    const uint32_t a_off = (uint32_t)((wm * 64 + (lane & 15)) * ROWB + (lane >> 4) * 16);
    const uint32_t b_off = (uint32_t)((wn * 64 + ((lane >> 4) << 3) + (lane & 7)) * ROWB
                                      + ((lane >> 3) & 1) * 16);

    auto load_stage = [&](int slot, int k0) {
        uint32_t sa = sd + slot * STAGE_BYTES;
        const uint8_t* gx = g_x8 + (size_t)bi * DDIM + k0;
        const uint8_t* gy = g_y8 + (size_t)bj * DDIM + k0;
#pragma unroll
        for (int t = 0; t < 4; t++) {
            int r = r0 + t * 32;
            cpa16(sa + r * ROWB + c0 * 16,          gx + (size_t)r * DDIM + c0 * 16);
            cpa16(sa + ABYTES + r * ROWB + c0 * 16, gy + (size_t)r * DDIM + c0 * 16);
        }
        asm volatile("cp.async.commit_group;" ::: "memory");
    };

    float d[128];
#pragma unroll
    for (int i = 0; i < 128; i++) d[i] = 0.f;

    // prologue: fill stages 0..2
    load_stage(0, 0);
    load_stage(1, BK);
    load_stage(2, 2 * BK);

    // norms staging
    snx[tid] = g_xsq[bi + tid];
    sny[tid] = g_ysq[bj + tid];

    uint32_t Af[2][4][4], Bf[2][4][4];

#pragma unroll 1
    for (int it = 0; it < NK; ++it) {
        if (it < NK - 2) asm volatile("cp.async.wait_group 2;" ::: "memory");
        else if (it == NK - 2) asm volatile("cp.async.wait_group 1;" ::: "memory");
        else asm volatile("cp.async.wait_group 0;" ::: "memory");
        __syncthreads();

        if (it + 3 < NK) load_stage((it + 3) & (STAGES - 1), (it + 3) * BK);

        const uint32_t sa  = sd + (it & (STAGES - 1)) * STAGE_BYTES;
        const uint32_t sbB = sa + ABYTES;

        // Fragment loads for both k32-slices (ks*32 bytes apart).
#pragma unroll
        for (int ks = 0; ks < 2; ks++) {
#pragma unroll
            for (int mt = 0; mt < 4; mt++)
                LDSM_X4(Af[ks][mt][0], Af[ks][mt][1], Af[ks][mt][2], Af[ks][mt][3],
                        sa + a_off + mt * 16 * ROWB + ks * 32);
#pragma unroll
            for (int ntp = 0; ntp < 4; ntp++)
                LDSM_X4(Bf[ks][ntp][0], Bf[ks][ntp][1], Bf[ks][ntp][2], Bf[ks][ntp][3],
                        sbB + b_off + ntp * 16 * ROWB + ks * 32);
        }

#pragma unroll
        for (int ks = 0; ks < 2; ks++)
#pragma unroll
            for (int mt = 0; mt < 4; mt++)
#pragma unroll
                for (int ntp = 0; ntp < 4; ntp++) {
                    MMA16832(&d[(mt * 8 + 2 * ntp) * 4],
                             Af[ks][mt][0], Af[ks][mt][1], Af[ks][mt][2], Af[ks][mt][3],
                             Bf[ks][ntp][0], Bf[ks][ntp][1]);
                    MMA16832(&d[(mt * 8 + 2 * ntp + 1) * 4],
                             Af[ks][mt][0], Af[ks][mt][1], Af[ks][mt][2], Af[ks][mt][3],
                             Bf[ks][ntp][2], Bf[ks][ntp][3]);
                }
    }

    __syncthreads();  // pipeline drained; snx/sny visible

    // ---- fused epilogue: exp(-max(nx + ny - 2*dot, 0)), float2 stores ----
    const int rq = lane >> 2;
    const int cq = (lane & 3) * 2;
#pragma unroll
    for (int mt = 0; mt < 4; mt++) {
#pragma unroll
        for (int half = 0; half < 2; half++) {
            const int row = wm * 64 + mt * 16 + half * 8 + rq;
            const float nx = snx[row];
            float* orow = O + (size_t)(bi + row) * 8192 + bj;
#pragma unroll
            for (int n8 = 0; n8 < 8; n8++) {
                const int col = wn * 64 + n8 * 8 + cq;
                float d0 = d[(mt * 8 + n8) * 4 + half * 2 + 0];
                float d1 = d[(mt * 8 + n8) * 4 + half * 2 + 1];
                float s0 = fmaxf(fmaf(-2.f, d0, nx + sny[col]),     0.f);
                float s1 = fmaxf(fmaf(-2.f, d1, nx + sny[col + 1]), 0.f);
                float2 e = make_float2(__expf(-s0), __expf(-s1));
                *reinterpret_cast<float2*>(orow + col) = e;
            }
        }
    }
}

// ---------------------------------------------------------------------------
extern "C" void kernel_launch(void* const* d_in, const int* in_sizes, int n_in,
                              void* d_out, int out_size) {
    const float* x = (const float*)d_in[0];
    const float* y = (const float*)d_in[1];
    float* out = (float*)d_out;

    cudaFuncSetAttribute(rbf_mma_kernel,
                         cudaFuncAttributeMaxDynamicSharedMemorySize, SMEM_DYN);

    prep_kernel<<<NROWS * 2 / 8, 256>>>(x, y);
    rbf_mma_kernel<<<dim3(8192 / BN, 8192 / BM), 128, SMEM_DYN>>>(out);
}